// round 16
// baseline (speedup 1.0000x reference)
#include <cuda_runtime.h>
#include <cuda.h>
#include <cstdint>
#include <cstring>

#define NN 5000
#define BT 128
#define SPD 132          // S row stride (floats)
#define NPAD 5120
#define NTHREADS 512
#define NMAT 12
#define SLOTB 65536u     // bytes per dense SW128 tile slot (128x128 f32)
#define SFL 49152        // float offset of S region (after 3 slots)
#define SGRP 4224        // floats per S group (2 halves x 16 x 132)

struct TMaps { CUtensorMap m[NMAT]; };

__device__ float g_St[2][16][NPAD];   // transposed supports; pad rows zero

// ---------------- helpers ----------------
__device__ __forceinline__ uint32_t f2tf32(float x) {
    uint32_t r;
    asm("cvt.rna.tf32.f32 %0, %1;" : "=r"(r) : "f"(x));
    return r;
}
__device__ __forceinline__ void mma_tf32(float* d, uint32_t a0, uint32_t a1,
                                         uint32_t a2, uint32_t a3,
                                         uint32_t b0, uint32_t b1) {
    asm volatile(
        "mma.sync.aligned.m16n8k8.row.col.f32.tf32.tf32.f32 "
        "{%0,%1,%2,%3}, {%4,%5,%6,%7}, {%8,%9}, {%0,%1,%2,%3};"
        : "+f"(d[0]), "+f"(d[1]), "+f"(d[2]), "+f"(d[3])
        : "r"(a0), "r"(a1), "r"(a2), "r"(a3), "r"(b0), "r"(b1));
}
__device__ __forceinline__ void red_add_v2(float* p, float x, float y) {
    asm volatile("red.global.add.v2.f32 [%0], {%1, %2};"
                 :: "l"(p), "f"(x), "f"(y) : "memory");
}
__device__ __forceinline__ void mbar_init(uint32_t mbar, uint32_t cnt) {
    asm volatile("mbarrier.init.shared.b64 [%0], %1;"
                 :: "r"(mbar), "r"(cnt) : "memory");
}
__device__ __forceinline__ void mbar_expect_tx(uint32_t mbar, uint32_t bytes) {
    asm volatile("mbarrier.arrive.expect_tx.shared.b64 _, [%0], %1;"
                 :: "r"(mbar), "r"(bytes) : "memory");
}
__device__ __forceinline__ void mbar_arrive(uint32_t mbar) {
    asm volatile("mbarrier.arrive.release.cta.shared::cta.b64 _, [%0];"
                 :: "r"(mbar) : "memory");
}
__device__ __forceinline__ void tma2d(uint32_t dst, const void* map,
                                      int x, int y, uint32_t mbar) {
    asm volatile(
        "cp.async.bulk.tensor.2d.shared::cta.global.tile.mbarrier::complete_tx::bytes "
        "[%0], [%1, {%2, %3}], [%4];"
        :: "r"(dst), "l"(map), "r"(x), "r"(y), "r"(mbar) : "memory");
}
__device__ __forceinline__ void mbar_wait(uint32_t mbar, uint32_t parity) {
    uint32_t done;
    asm volatile(
        "{\n\t.reg .pred p;\n\t"
        "mbarrier.try_wait.parity.acquire.cta.shared::cta.b64 p, [%1], %2;\n\t"
        "selp.b32 %0, 1, 0, p;\n\t}"
        : "=r"(done) : "r"(mbar), "r"(parity) : "memory");
    if (!done) {
        asm volatile(
            "{\n\t.reg .pred P1;\n\t"
            "WAIT_LOOP_%=:\n\t"
            "mbarrier.try_wait.parity.acquire.cta.shared::cta.b64 P1, [%0], %1, 0x989680;\n\t"
            "@P1 bra.uni WAIT_DONE_%=;\n\t"
            "bra.uni WAIT_LOOP_%=;\n\t"
            "WAIT_DONE_%=:\n\t}"
            :: "r"(mbar), "r"(parity) : "memory");
    }
}

// ---------------- prep: g_St = (feature @ W)^T, bias-init out ----------------
__global__ void fame_prep(const float* __restrict__ feature,
                          const float* __restrict__ W3, const float* __restrict__ b3,
                          const float* __restrict__ W1, const float* __restrict__ b1,
                          float* __restrict__ out) {
    __shared__ float fsm[128];
    const int row = blockIdx.x;
    const int t = threadIdx.x;
    fsm[t] = feature[row * 128 + t];
    __syncthreads();
    if (t < 32) {
        const int g = t >> 4;
        const int c = t & 15;
        const float* __restrict__ W = g ? W1 : W3;
        float s = 0.f;
#pragma unroll 16
        for (int k = 0; k < 128; k++) s += fsm[k] * W[k * 16 + c];
        g_St[g][c][row] = s;
    } else if (t < 64) {
        const int c = t - 32;
        out[row * 32 + c] = (c < 16) ? b3[c] : b1[c - 16];
    }
}

// ---- main: sync-free producer/consumer TMA ring, reg-B TF32 mma ----
__global__ __launch_bounds__(NTHREADS, 1)
void fame_main(const __grid_constant__ TMaps maps,
               const float* __restrict__ wA, const float* __restrict__ wB,
               float* __restrict__ out)
{
    extern __shared__ __align__(1024) float smem[];
    const uint32_t smem_base = (uint32_t)__cvta_generic_to_shared(smem);
    const uint32_t full0  = smem_base + (uint32_t)(SFL + 2 * SGRP) * 4u;
    const uint32_t empty0 = full0 + 24u;

    const int t = threadIdx.x;
    const int wid = t >> 5, lane = t & 31;
    const int p = lane >> 2, q = lane & 3;
    const int side = wid >> 3;               // 0: direct GEMM, 1: transpose GEMM
    const int wsub = wid & 7;                // 16-row slice within side
    const int i0 = blockIdx.y * BT, j0 = blockIdx.x * BT;

    if (t < 3) mbar_init(full0 + 8u * (uint32_t)t, 1u);
    else if (t < 6) mbar_init(empty0 + 8u * (uint32_t)(t - 3), 16u);

    // ---- stage BOTH groups' unscaled tf32 S^T tiles (once, before loop) ----
    for (int idx = t; idx < 2 * SGRP; idx += NTHREADS) {
        const int g = idx / SGRP;
        const int rem = idx - g * SGRP;
        const int half = rem / (16 * SPD);
        const int r2 = rem - half * (16 * SPD);
        const int n = r2 / SPD, k = r2 - n * SPD;
        if (k < 128) {
            const float v = g_St[g][n][(half ? i0 : j0) + k];
            smem[SFL + idx] = __uint_as_float(f2tf32(v));
        }
    }
    __syncthreads();   // barriers live + S staged (only sync in the kernel)

    // ---- single-thread TMA issue: 1 expect_tx + 4 box loads per tile ----
    auto issue_tile = [&](int m) {
        const int slot = m % 3;
        const uint32_t mb = full0 + 8u * (uint32_t)slot;
        const uint32_t dst = smem_base + (uint32_t)slot * SLOTB;
        mbar_expect_tx(mb, SLOTB);
#pragma unroll
        for (int c = 0; c < 4; c++)
            tma2d(dst + (uint32_t)c * 16384u, &maps.m[m], j0 + 32 * c, i0, mb);
    };

    uint32_t breg[64];
    auto load_B = [&](int g) {
        const float* __restrict__ Bp = smem + SFL + g * SGRP
                                     + side * (16 * SPD) + p * SPD + q;
#pragma unroll
        for (int ks = 0; ks < 16; ks++) {
            const int kb = 8 * ks;
            breg[4 * ks + 0] = __float_as_uint(Bp[kb]);
            breg[4 * ks + 1] = __float_as_uint(Bp[kb + 4]);
            breg[4 * ks + 2] = __float_as_uint(Bp[8 * SPD + kb]);
            breg[4 * ks + 3] = __float_as_uint(Bp[8 * SPD + kb + 4]);
        }
    };

    float acc[8], araw[8];
#pragma unroll
    for (int a = 0; a < 8; a++) { acc[a] = 0.f; araw[a] = 0.f; }

    auto flush = [&](int goff) {
        const int base_row = ((side == 0) ? i0 : j0) + 16 * wsub;
#pragma unroll
        for (int ng = 0; ng < 2; ng++) {
            float* ap = acc + 4 * ng;
            const int col = goff + 8 * ng + 2 * q;
            const int r0 = base_row + p;
            if (r0 < NN)     red_add_v2(out + (size_t)r0 * 32 + col, ap[0], ap[1]);
            if (r0 + 8 < NN) red_add_v2(out + (size_t)(r0 + 8) * 32 + col, ap[2], ap[3]);
        }
#pragma unroll
        for (int a = 0; a < 8; a++) acc[a] = 0.f;
    };

    // precomputed SW128 addressing constants (dense TMA slot layout)
    const uint32_t s0_base = (uint32_t)((16 * wsub + p) * 128);
    const uint32_t s0_rxor = (uint32_t)(p << 4);
    const uint32_t s0_q4 = (uint32_t)(4 * q);
    const uint32_t s1_chunk = (uint32_t)((wsub >> 1) * 16384);
    const uint32_t s1_c4 = (uint32_t)((16 * (wsub & 1) + p) * 4);
    const uint32_t s1_o0 = s1_chunk + (uint32_t)(q * 128) + (s1_c4 ^ (uint32_t)(q << 4));
    const uint32_t s1_o1 = s1_chunk + (uint32_t)(q * 128) + ((s1_c4 + 32u) ^ (uint32_t)(q << 4));
    const uint32_t s1_o2 = s1_chunk + (uint32_t)((q + 4) * 128) + (s1_c4 ^ (uint32_t)((q + 4) << 4));
    const uint32_t s1_o3 = s1_chunk + (uint32_t)((q + 4) * 128) + ((s1_c4 + 32u) ^ (uint32_t)((q + 4) << 4));

    // ---- prologue: fill all 3 slots, B group 0 in regs ----
    if (t == 0) { issue_tile(0); issue_tile(1); issue_tile(2); }
    load_B(0);

    for (int m = 0; m < NMAT; m++) {
        const int slot = m % 3;
        const uint32_t pf = (uint32_t)((m / 3) & 1);
        if (m == 3) load_B(1);                 // group switch, per-warp, no sync

        mbar_wait(full0 + 8u * (uint32_t)slot, pf);

        const char* __restrict__ Tb = (const char*)smem + (uint32_t)slot * SLOTB;
        const float w = (m < 3) ? wA[m] : wB[m - 3];

        if (side == 0) {
#pragma unroll
            for (int ks = 0; ks < 16; ks++) {
                const uint32_t chunk = (uint32_t)((ks >> 2) * 16384);
                const uint32_t cb0 = (uint32_t)((ks & 3) * 32) + s0_q4;
                const uint32_t off0 = chunk + s0_base + (cb0 ^ s0_rxor);
                const uint32_t off2 = chunk + s0_base + ((cb0 + 16u) ^ s0_rxor);
                const uint32_t a0 = __float_as_uint(*(const float*)(Tb + off0));
                const uint32_t a1 = __float_as_uint(*(const float*)(Tb + off0 + 1024));
                const uint32_t a2 = __float_as_uint(*(const float*)(Tb + off2));
                const uint32_t a3 = __float_as_uint(*(const float*)(Tb + off2 + 1024));
                mma_tf32(araw,     a0, a1, a2, a3, breg[4 * ks + 0], breg[4 * ks + 1]);
                mma_tf32(araw + 4, a0, a1, a2, a3, breg[4 * ks + 2], breg[4 * ks + 3]);
            }
        } else {
#pragma unroll
            for (int ks = 0; ks < 16; ks++) {
                const uint32_t rb = (uint32_t)(ks * 1024);
                const uint32_t a0 = __float_as_uint(*(const float*)(Tb + s1_o0 + rb));
                const uint32_t a1 = __float_as_uint(*(const float*)(Tb + s1_o1 + rb));
                const uint32_t a2 = __float_as_uint(*(const float*)(Tb + s1_o2 + rb));
                const uint32_t a3 = __float_as_uint(*(const float*)(Tb + s1_o3 + rb));
                mma_tf32(araw,     a0, a1, a2, a3, breg[4 * ks + 0], breg[4 * ks + 1]);
                mma_tf32(araw + 4, a0, a1, a2, a3, breg[4 * ks + 2], breg[4 * ks + 3]);
            }
        }

        // fold matrix weight into the running group accumulator
#pragma unroll
        for (int a = 0; a < 8; a++) { acc[a] = fmaf(w, araw[a], acc[a]); araw[a] = 0.f; }

        if (m == 2) flush(0);          // group A -> cols 0..15
        if (m == NMAT - 1) flush(16);  // group B -> cols 16..31

        // consumer arrive: this warp is done reading slot m
        if (lane == 0) mbar_arrive(empty0 + 8u * (uint32_t)slot);

        // producer (thread 0): refill this slot with tile m+3 once all 16 warps arrived
        if (t == 0 && m + 3 < NMAT) {
            mbar_wait(empty0 + 8u * (uint32_t)slot, pf);
            issue_tile(m + 3);
        }
    }
}

// ---------------- host ----------------
typedef CUresult (*PFN_tmapEncode)(
    CUtensorMap*, CUtensorMapDataType, cuuint32_t, void*,
    const cuuint64_t*, const cuuint64_t*, const cuuint32_t*, const cuuint32_t*,
    CUtensorMapInterleave, CUtensorMapSwizzle, CUtensorMapL2promotion,
    CUtensorMapFloatOOBfill);

extern "C" void kernel_launch(void* const* d_in, const int* in_sizes, int n_in,
                              void* d_out, int out_size) {
    const float* feature = (const float*)d_in[0];  // [5000,128]
    const float* A       = (const float*)d_in[1];  // [3,5000,5000]
    const float* At      = (const float*)d_in[2];  // [9,5000,5000]
    const float* wb2     = (const float*)d_in[3];  // [3,1]
    const float* wb      = (const float*)d_in[4];  // [9,1]
    const float* W3      = (const float*)d_in[5];  // [128,16]
    const float* b3      = (const float*)d_in[6];  // [16]
    const float* W1      = (const float*)d_in[7];  // [128,16]
    const float* b1      = (const float*)d_in[8];  // [16]
    float* out = (float*)d_out;                    // [5000,32]

    fame_prep<<<NN, 128>>>(feature, W3, b3, W1, b1, out);

    static PFN_tmapEncode pfn = nullptr;
    if (!pfn) {
        cudaDriverEntryPointQueryResult qres;
        void* fp = nullptr;
        cudaGetDriverEntryPointByVersion("cuTensorMapEncodeTiled", &fp, 12000,
                                         cudaEnableDefault, &qres);
        pfn = (PFN_tmapEncode)fp;
    }
    TMaps maps;
    const cuuint64_t gdim[2] = {(cuuint64_t)NN, (cuuint64_t)NN};
    const cuuint64_t gstr[1] = {(cuuint64_t)NN * 4};
    const cuuint32_t box[2] = {32u, 128u};
    const cuuint32_t estr[2] = {1u, 1u};
    for (int m = 0; m < NMAT; m++) {
        void* base = (void*)((m < 3)
            ? A  + (size_t)m       * (size_t)NN * (size_t)NN
            : At + (size_t)(m - 3) * (size_t)NN * (size_t)NN);
        pfn(&maps.m[m], CU_TENSOR_MAP_DATA_TYPE_FLOAT32, 2, base,
            gdim, gstr, box, estr,
            CU_TENSOR_MAP_INTERLEAVE_NONE, CU_TENSOR_MAP_SWIZZLE_128B,
            CU_TENSOR_MAP_L2_PROMOTION_L2_128B, CU_TENSOR_MAP_FLOAT_OOB_FILL_NONE);
    }

    // 3 dense slots (192KB) + 2 S groups (33KB) + 6 mbarriers (48B)
    const int smem_bytes = (int)(3 * SLOTB) + 2 * SGRP * (int)sizeof(float) + 48;
    cudaFuncSetAttribute(fame_main, cudaFuncAttributeMaxDynamicSharedMemorySize, smem_bytes);
    dim3 grid((NN + BT - 1) / BT, (NN + BT - 1) / BT);
    fame_main<<<grid, NTHREADS, smem_bytes>>>(maps, wb2, wb, out);
}

// round 17
// speedup vs baseline: 1.0024x; 1.0024x over previous
#include <cuda_runtime.h>
#include <cuda.h>
#include <cstdint>
#include <cstring>

#define NN 5000
#define BT 128
#define SPD 132          // S row stride (floats)
#define NPAD 5120
#define NTHREADS 512
#define NMAT 12
#define SLOTB 65536u     // bytes per dense SW128 tile slot (128x128 f32)
#define SFL 49152        // float offset of S region (after 3 slots)
#define SGRP 4224        // floats per S group (2 halves x 16 x 132)

struct TMaps { CUtensorMap m[NMAT]; };

__device__ float g_St[2][16][NPAD];   // transposed supports; pad rows zero

// ---------------- helpers ----------------
__device__ __forceinline__ uint32_t f2tf32(float x) {
    uint32_t r;
    asm("cvt.rna.tf32.f32 %0, %1;" : "=r"(r) : "f"(x));
    return r;
}
__device__ __forceinline__ void mma_tf32(float* d, uint32_t a0, uint32_t a1,
                                         uint32_t a2, uint32_t a3,
                                         uint32_t b0, uint32_t b1) {
    asm volatile(
        "mma.sync.aligned.m16n8k8.row.col.f32.tf32.tf32.f32 "
        "{%0,%1,%2,%3}, {%4,%5,%6,%7}, {%8,%9}, {%0,%1,%2,%3};"
        : "+f"(d[0]), "+f"(d[1]), "+f"(d[2]), "+f"(d[3])
        : "r"(a0), "r"(a1), "r"(a2), "r"(a3), "r"(b0), "r"(b1));
}
__device__ __forceinline__ void red_add_v2(float* p, float x, float y) {
    asm volatile("red.global.add.v2.f32 [%0], {%1, %2};"
                 :: "l"(p), "f"(x), "f"(y) : "memory");
}
__device__ __forceinline__ void mbar_init(uint32_t mbar, uint32_t cnt) {
    asm volatile("mbarrier.init.shared.b64 [%0], %1;"
                 :: "r"(mbar), "r"(cnt) : "memory");
}
__device__ __forceinline__ void mbar_expect_tx(uint32_t mbar, uint32_t bytes) {
    asm volatile("mbarrier.arrive.expect_tx.shared.b64 _, [%0], %1;"
                 :: "r"(mbar), "r"(bytes) : "memory");
}
__device__ __forceinline__ void tma2d(uint32_t dst, const void* map,
                                      int x, int y, uint32_t mbar) {
    asm volatile(
        "cp.async.bulk.tensor.2d.shared::cta.global.tile.mbarrier::complete_tx::bytes "
        "[%0], [%1, {%2, %3}], [%4];"
        :: "r"(dst), "l"(map), "r"(x), "r"(y), "r"(mbar) : "memory");
}
__device__ __forceinline__ void mbar_wait(uint32_t mbar, uint32_t parity) {
    uint32_t done;
    asm volatile(
        "{\n\t.reg .pred p;\n\t"
        "mbarrier.try_wait.parity.acquire.cta.shared::cta.b64 p, [%1], %2;\n\t"
        "selp.b32 %0, 1, 0, p;\n\t}"
        : "=r"(done) : "r"(mbar), "r"(parity) : "memory");
    if (!done) {
        asm volatile(
            "{\n\t.reg .pred P1;\n\t"
            "WAIT_LOOP_%=:\n\t"
            "mbarrier.try_wait.parity.acquire.cta.shared::cta.b64 P1, [%0], %1, 0x989680;\n\t"
            "@P1 bra.uni WAIT_DONE_%=;\n\t"
            "bra.uni WAIT_LOOP_%=;\n\t"
            "WAIT_DONE_%=:\n\t}"
            :: "r"(mbar), "r"(parity) : "memory");
    }
}

// ---------------- prep: g_St = (feature @ W)^T, bias-init out ----------------
__global__ void fame_prep(const float* __restrict__ feature,
                          const float* __restrict__ W3, const float* __restrict__ b3,
                          const float* __restrict__ W1, const float* __restrict__ b1,
                          float* __restrict__ out) {
    __shared__ float fsm[128];
    const int row = blockIdx.x;
    const int t = threadIdx.x;
    fsm[t] = feature[row * 128 + t];
    __syncthreads();
    if (t < 32) {
        const int g = t >> 4;
        const int c = t & 15;
        const float* __restrict__ W = g ? W1 : W3;
        float s = 0.f;
#pragma unroll 16
        for (int k = 0; k < 128; k++) s += fsm[k] * W[k * 16 + c];
        g_St[g][c][row] = s;
    } else if (t < 64) {
        const int c = t - 32;
        out[row * 32 + c] = (c < 16) ? b3[c] : b1[c - 16];
    }
}

// ---- main: depth-3 TMA ring (issue after bar, 3 tiles in flight), reg-B TF32 mma ----
__global__ __launch_bounds__(NTHREADS, 1)
void fame_main(const __grid_constant__ TMaps maps,
               const float* __restrict__ wA, const float* __restrict__ wB,
               float* __restrict__ out)
{
    extern __shared__ __align__(1024) float smem[];
    const uint32_t smem_base = (uint32_t)__cvta_generic_to_shared(smem);
    const uint32_t full0 = smem_base + (uint32_t)(SFL + 2 * SGRP) * 4u;

    const int t = threadIdx.x;
    const int wid = t >> 5, lane = t & 31;
    const int p = lane >> 2, q = lane & 3;
    const int side = wid >> 3;               // 0: direct GEMM, 1: transpose GEMM
    const int wsub = wid & 7;                // 16-row slice within side
    const int i0 = blockIdx.y * BT, j0 = blockIdx.x * BT;

    if (t < 3) mbar_init(full0 + 8u * (uint32_t)t, 4u);

    // ---- stage BOTH groups' unscaled tf32 S^T tiles (once) ----
    for (int idx = t; idx < 2 * SGRP; idx += NTHREADS) {
        const int g = idx / SGRP;
        const int rem = idx - g * SGRP;
        const int half = rem / (16 * SPD);
        const int r2 = rem - half * (16 * SPD);
        const int n = r2 / SPD, k = r2 - n * SPD;
        if (k < 128) {
            const float v = g_St[g][n][(half ? i0 : j0) + k];
            smem[SFL + idx] = __uint_as_float(f2tf32(v));
        }
    }
    __syncthreads();   // barriers live + S staged

    // ---- TMA: 4 box loads (32 cols x 128 rows, SW128) per tile, by t<4 ----
    auto issue_tile = [&](int m) {
        if (t < 4) {
            const int slot = m % 3;
            const uint32_t mb = full0 + 8u * (uint32_t)slot;
            const uint32_t dst = smem_base + (uint32_t)slot * SLOTB
                               + (uint32_t)t * 16384u;
            mbar_expect_tx(mb, 16384u);
            tma2d(dst, &maps.m[m], j0 + 32 * t, i0, mb);
        }
    };

    uint32_t breg[64];
    auto load_B = [&](int g) {
        const float* __restrict__ Bp = smem + SFL + g * SGRP
                                     + side * (16 * SPD) + p * SPD + q;
#pragma unroll
        for (int ks = 0; ks < 16; ks++) {
            const int kb = 8 * ks;
            breg[4 * ks + 0] = __float_as_uint(Bp[kb]);
            breg[4 * ks + 1] = __float_as_uint(Bp[kb + 4]);
            breg[4 * ks + 2] = __float_as_uint(Bp[8 * SPD + kb]);
            breg[4 * ks + 3] = __float_as_uint(Bp[8 * SPD + kb + 4]);
        }
    };

    float acc[8], araw[8];
#pragma unroll
    for (int a = 0; a < 8; a++) { acc[a] = 0.f; araw[a] = 0.f; }

    auto flush = [&](int goff) {
        const int base_row = ((side == 0) ? i0 : j0) + 16 * wsub;
#pragma unroll
        for (int ng = 0; ng < 2; ng++) {
            float* ap = acc + 4 * ng;
            const int col = goff + 8 * ng + 2 * q;
            const int r0 = base_row + p;
            if (r0 < NN)     red_add_v2(out + (size_t)r0 * 32 + col, ap[0], ap[1]);
            if (r0 + 8 < NN) red_add_v2(out + (size_t)(r0 + 8) * 32 + col, ap[2], ap[3]);
        }
#pragma unroll
        for (int a = 0; a < 8; a++) acc[a] = 0.f;
    };

    // precomputed SW128 addressing constants (dense TMA slot layout)
    const uint32_t s0_base = (uint32_t)((16 * wsub + p) * 128);
    const uint32_t s0_rxor = (uint32_t)(p << 4);
    const uint32_t s0_q4 = (uint32_t)(4 * q);
    const uint32_t s1_chunk = (uint32_t)((wsub >> 1) * 16384);
    const uint32_t s1_c4 = (uint32_t)((16 * (wsub & 1) + p) * 4);
    const uint32_t s1_o0 = s1_chunk + (uint32_t)(q * 128) + (s1_c4 ^ (uint32_t)(q << 4));
    const uint32_t s1_o1 = s1_chunk + (uint32_t)(q * 128) + ((s1_c4 + 32u) ^ (uint32_t)(q << 4));
    const uint32_t s1_o2 = s1_chunk + (uint32_t)((q + 4) * 128) + (s1_c4 ^ (uint32_t)((q + 4) << 4));
    const uint32_t s1_o3 = s1_chunk + (uint32_t)((q + 4) * 128) + ((s1_c4 + 32u) ^ (uint32_t)((q + 4) << 4));

    // ---- prologue: fill ALL THREE slots, B group 0 in regs ----
    issue_tile(0);
    issue_tile(1);
    issue_tile(2);
    load_B(0);

    for (int m = 0; m < NMAT; m++) {
        const int slot = m % 3;
        if (m == 3) load_B(1);                 // group switch, per-warp, no sync

        mbar_wait(full0 + 8u * (uint32_t)slot, (uint32_t)((m / 3) & 1));

        const char* __restrict__ Tb = (const char*)smem + (uint32_t)slot * SLOTB;
        const float w = (m < 3) ? wA[m] : wB[m - 3];

        if (side == 0) {
#pragma unroll
            for (int ks = 0; ks < 16; ks++) {
                const uint32_t chunk = (uint32_t)((ks >> 2) * 16384);
                const uint32_t cb0 = (uint32_t)((ks & 3) * 32) + s0_q4;
                const uint32_t off0 = chunk + s0_base + (cb0 ^ s0_rxor);
                const uint32_t off2 = chunk + s0_base + ((cb0 + 16u) ^ s0_rxor);
                const uint32_t a0 = __float_as_uint(*(const float*)(Tb + off0));
                const uint32_t a1 = __float_as_uint(*(const float*)(Tb + off0 + 1024));
                const uint32_t a2 = __float_as_uint(*(const float*)(Tb + off2));
                const uint32_t a3 = __float_as_uint(*(const float*)(Tb + off2 + 1024));
                mma_tf32(araw,     a0, a1, a2, a3, breg[4 * ks + 0], breg[4 * ks + 1]);
                mma_tf32(araw + 4, a0, a1, a2, a3, breg[4 * ks + 2], breg[4 * ks + 3]);
            }
        } else {
#pragma unroll
            for (int ks = 0; ks < 16; ks++) {
                const uint32_t rb = (uint32_t)(ks * 1024);
                const uint32_t a0 = __float_as_uint(*(const float*)(Tb + s1_o0 + rb));
                const uint32_t a1 = __float_as_uint(*(const float*)(Tb + s1_o1 + rb));
                const uint32_t a2 = __float_as_uint(*(const float*)(Tb + s1_o2 + rb));
                const uint32_t a3 = __float_as_uint(*(const float*)(Tb + s1_o3 + rb));
                mma_tf32(araw,     a0, a1, a2, a3, breg[4 * ks + 0], breg[4 * ks + 1]);
                mma_tf32(araw + 4, a0, a1, a2, a3, breg[4 * ks + 2], breg[4 * ks + 3]);
            }
        }

        // fold matrix weight into the running group accumulator
#pragma unroll
        for (int a = 0; a < 8; a++) { acc[a] = fmaf(w, araw[a], acc[a]); araw[a] = 0.f; }

        if (m == 2) flush(0);          // group A -> cols 0..15
        if (m == NMAT - 1) flush(16);  // group B -> cols 16..31

        // all warps done reading slot m -> refill it with tile m+3 (off critical path)
        __syncthreads();
        if (m + 3 < NMAT) issue_tile(m + 3);
    }
}

// ---------------- host ----------------
typedef CUresult (*PFN_tmapEncode)(
    CUtensorMap*, CUtensorMapDataType, cuuint32_t, void*,
    const cuuint64_t*, const cuuint64_t*, const cuuint32_t*, const cuuint32_t*,
    CUtensorMapInterleave, CUtensorMapSwizzle, CUtensorMapL2promotion,
    CUtensorMapFloatOOBfill);

extern "C" void kernel_launch(void* const* d_in, const int* in_sizes, int n_in,
                              void* d_out, int out_size) {
    const float* feature = (const float*)d_in[0];  // [5000,128]
    const float* A       = (const float*)d_in[1];  // [3,5000,5000]
    const float* At      = (const float*)d_in[2];  // [9,5000,5000]
    const float* wb2     = (const float*)d_in[3];  // [3,1]
    const float* wb      = (const float*)d_in[4];  // [9,1]
    const float* W3      = (const float*)d_in[5];  // [128,16]
    const float* b3      = (const float*)d_in[6];  // [16]
    const float* W1      = (const float*)d_in[7];  // [128,16]
    const float* b1      = (const float*)d_in[8];  // [16]
    float* out = (float*)d_out;                    // [5000,32]

    fame_prep<<<NN, 128>>>(feature, W3, b3, W1, b1, out);

    static PFN_tmapEncode pfn = nullptr;
    if (!pfn) {
        cudaDriverEntryPointQueryResult qres;
        void* fp = nullptr;
        cudaGetDriverEntryPointByVersion("cuTensorMapEncodeTiled", &fp, 12000,
                                         cudaEnableDefault, &qres);
        pfn = (PFN_tmapEncode)fp;
    }
    TMaps maps;
    const cuuint64_t gdim[2] = {(cuuint64_t)NN, (cuuint64_t)NN};
    const cuuint64_t gstr[1] = {(cuuint64_t)NN * 4};
    const cuuint32_t box[2] = {32u, 128u};
    const cuuint32_t estr[2] = {1u, 1u};
    for (int m = 0; m < NMAT; m++) {
        void* base = (void*)((m < 3)
            ? A  + (size_t)m       * (size_t)NN * (size_t)NN
            : At + (size_t)(m - 3) * (size_t)NN * (size_t)NN);
        pfn(&maps.m[m], CU_TENSOR_MAP_DATA_TYPE_FLOAT32, 2, base,
            gdim, gstr, box, estr,
            CU_TENSOR_MAP_INTERLEAVE_NONE, CU_TENSOR_MAP_SWIZZLE_128B,
            CU_TENSOR_MAP_L2_PROMOTION_L2_128B, CU_TENSOR_MAP_FLOAT_OOB_FILL_NONE);
    }

    // 3 dense slots (192KB) + 2 S groups (33KB) + 3 mbarriers (24B)
    const int smem_bytes = (int)(3 * SLOTB) + 2 * SGRP * (int)sizeof(float) + 24;
    cudaFuncSetAttribute(fame_main, cudaFuncAttributeMaxDynamicSharedMemorySize, smem_bytes);
    dim3 grid((NN + BT - 1) / BT, (NN + BT - 1) / BT);
    fame_main<<<grid, NTHREADS, smem_bytes>>>(maps, wb2, wb, out);
}